// round 1
// baseline (speedup 1.0000x reference)
#include <cuda_runtime.h>

#define N_NODES  100000
#define IN_DIM   256
#define OUT_DIM  128
#define FEAT_NNZ 1000000
#define ADJ_NNZ  1600000

// Scratch for XW = X @ W  (51.2 MB) — __device__ global per allocation rules.
__device__ float g_xw[(size_t)N_NODES * OUT_DIM];

// ---------------------------------------------------------------------------
// Kernel 0: zero XW scratch and the output accumulator (d_out is poisoned).
// ---------------------------------------------------------------------------
__global__ void zero_kernel(float4* __restrict__ out4) {
    size_t n4 = (size_t)N_NODES * OUT_DIM / 4;   // 3.2M float4
    size_t idx = (size_t)blockIdx.x * blockDim.x + threadIdx.x;
    if (idx < n4) {
        float4 z = make_float4(0.f, 0.f, 0.f, 0.f);
        ((float4*)g_xw)[idx] = z;
        out4[idx] = z;
    }
}

// ---------------------------------------------------------------------------
// Vectorized global reduction: one 16B RMW instead of 4 scalar atomicAdds.
// ---------------------------------------------------------------------------
__device__ __forceinline__ void red_add_v4(float* dst, float4 p) {
    asm volatile("red.global.add.v4.f32 [%0], {%1, %2, %3, %4};"
                 :: "l"(dst), "f"(p.x), "f"(p.y), "f"(p.z), "f"(p.w)
                 : "memory");
}

// ---------------------------------------------------------------------------
// SpMM1: for each feat nnz e: XW[row[e], :] += val[e] * W[col[e], :]
// One warp per nnz; each lane owns 4 consecutive output columns (float4).
// W row = 128 floats = 32 float4 — perfectly coalesced lane loads.
// ---------------------------------------------------------------------------
__global__ void spmm1_kernel(const float* __restrict__ vals,
                             const int*   __restrict__ rows,
                             const int*   __restrict__ cols,
                             const float4* __restrict__ W4) {
    int e = blockIdx.x * (blockDim.x >> 5) + (threadIdx.x >> 5);
    if (e >= FEAT_NNZ) return;
    int lane = threadIdx.x & 31;

    float v = __ldg(&vals[e]);          // broadcast within warp (L1 dedups)
    int   r = __ldg(&rows[e]);
    int   c = __ldg(&cols[e]);

    float4 w = __ldg(&W4[(size_t)c * 32 + lane]);
    float4 p = make_float4(v * w.x, v * w.y, v * w.z, v * w.w);
    red_add_v4(&g_xw[(size_t)r * OUT_DIM + lane * 4], p);
}

// ---------------------------------------------------------------------------
// SpMM2: for each adj nnz e: OUT[row[e], :] += val[e] * XW[col[e], :]
// Same warp-per-nnz layout. XW is L2-resident (51.2 MB < 126 MB L2).
// ---------------------------------------------------------------------------
__global__ void spmm2_kernel(const float* __restrict__ vals,
                             const int*   __restrict__ rows,
                             const int*   __restrict__ cols,
                             float* __restrict__ out) {
    int e = blockIdx.x * (blockDim.x >> 5) + (threadIdx.x >> 5);
    if (e >= ADJ_NNZ) return;
    int lane = threadIdx.x & 31;

    float v = __ldg(&vals[e]);
    int   r = __ldg(&rows[e]);
    int   c = __ldg(&cols[e]);

    float4 x = *(const float4*)&g_xw[(size_t)c * OUT_DIM + lane * 4];
    float4 p = make_float4(v * x.x, v * x.y, v * x.z, v * x.w);
    red_add_v4(&out[(size_t)r * OUT_DIM + lane * 4], p);
}

// ---------------------------------------------------------------------------
// Epilogue: out = relu(out + bias). bias is all-zeros in this dataset but we
// apply it anyway for correctness under any input.
// ---------------------------------------------------------------------------
__global__ void bias_relu_kernel(float4* __restrict__ out4,
                                 const float4* __restrict__ bias4) {
    size_t n4 = (size_t)N_NODES * OUT_DIM / 4;
    size_t idx = (size_t)blockIdx.x * blockDim.x + threadIdx.x;
    if (idx >= n4) return;
    int c4 = (int)(idx & 31);           // float4 index within the 128-col row
    float4 b = __ldg(&bias4[c4]);
    float4 v = out4[idx];
    v.x = fmaxf(v.x + b.x, 0.f);
    v.y = fmaxf(v.y + b.y, 0.f);
    v.z = fmaxf(v.z + b.z, 0.f);
    v.w = fmaxf(v.w + b.w, 0.f);
    out4[idx] = v;
}

extern "C" void kernel_launch(void* const* d_in, const int* in_sizes, int n_in,
                              void* d_out, int out_size) {
    const float* feat_vals = (const float*)d_in[0];
    const int*   feat_rows = (const int*)  d_in[1];
    const int*   feat_cols = (const int*)  d_in[2];
    const float* adj_vals  = (const float*)d_in[3];
    const int*   adj_rows  = (const int*)  d_in[4];
    const int*   adj_cols  = (const int*)  d_in[5];
    const float* weights   = (const float*)d_in[6];
    const float* bias_vec  = (const float*)d_in[7];
    float* out = (float*)d_out;

    const int threads = 256;
    const size_t n4 = (size_t)N_NODES * OUT_DIM / 4;
    const int zero_blocks = (int)((n4 + threads - 1) / threads);

    zero_kernel<<<zero_blocks, threads>>>((float4*)out);

    // 8 warps per block, one warp per nnz
    spmm1_kernel<<<(FEAT_NNZ + 7) / 8, threads>>>(feat_vals, feat_rows, feat_cols,
                                                  (const float4*)weights);
    spmm2_kernel<<<(ADJ_NNZ + 7) / 8, threads>>>(adj_vals, adj_rows, adj_cols, out);

    bias_relu_kernel<<<zero_blocks, threads>>>((float4*)out, (const float4*)bias_vec);
}